// round 1
// baseline (speedup 1.0000x reference)
#include <cuda_runtime.h>
#include <math.h>

#define N_CRIT  128
#define N_PAIRS 8128
#define N_TOT   (N_CRIT + N_PAIRS)   // 8256
#define N_VEC4  (N_TOT / 4)          // 2064
#define MIN_W   1e-7f

// Effective (constrained) weight vector: [wc_eff (128) | wint_eff (8128)]
__device__ float g_w[N_TOT];
__device__ float g_inv_sum;

// ---------------------------------------------------------------------------
// Prep: apply constraints, build contiguous weight vector, compute 1/sum.
// One block of 128 threads; thread i owns criterion i and triangle-row i.
// ---------------------------------------------------------------------------
__global__ void choquet_prep_kernel(const float* __restrict__ wc,
                                    const float* __restrict__ wint) {
    __shared__ float s_wc[N_CRIT];
    __shared__ float s_part[N_CRIT];
    const int i = threadIdx.x;

    float wce = wc[i];
    if (wce < 0.f) wce = MIN_W;
    s_wc[i] = wce;
    g_w[i]  = wce;
    __syncthreads();

    // Pair (i, j), i<j, row-major upper triangle.
    // Row i starts at offset i*(N-1) - i*(i-1)/2.
    const int base = i * (N_CRIT - 1) - (i * (i - 1)) / 2;
    float sum = wce;  // each thread contributes its own wc_eff once
    for (int j = i + 1; j < N_CRIT; j++) {
        const int p   = base + (j - i - 1);
        const float lo = fmaxf(-wce, -s_wc[j]);
        const float v  = fmaxf(wint[p], lo);
        g_w[N_CRIT + p] = v;
        sum += v;
    }

    s_part[i] = sum;
    __syncthreads();
    #pragma unroll
    for (int off = 64; off > 0; off >>= 1) {
        if (i < off) s_part[i] += s_part[i + off];
        __syncthreads();
    }
    if (i == 0) g_inv_sum = 1.0f / s_part[0];
}

// ---------------------------------------------------------------------------
// GEMV: one warp per row. 2064 float4 per row, ~65 per lane, unrolled for MLP.
// Epilogue: sigmoid(acc * inv_sum - thr).
// ---------------------------------------------------------------------------
__global__ void __launch_bounds__(256)
choquet_gemv_kernel(const float* __restrict__ x,
                    const float* __restrict__ thr,
                    float* __restrict__ out,
                    int rows) {
    const int warp = (blockIdx.x * blockDim.x + threadIdx.x) >> 5;
    const int lane = threadIdx.x & 31;
    if (warp >= rows) return;

    const float4* __restrict__ xr = reinterpret_cast<const float4*>(
        x + (size_t)warp * N_TOT);
    const float4* __restrict__ w4 = reinterpret_cast<const float4*>(g_w);

    float acc = 0.f;
    // N_VEC4 = 2064 = 64*32 + 16: main unrolled loop covers 64 iters/lane,
    // the tail covers lanes < 16.
    #pragma unroll 4
    for (int i = lane; i < 2048; i += 32) {
        const float4 a = xr[i];
        const float4 b = w4[i];
        acc = fmaf(a.x, b.x, acc);
        acc = fmaf(a.y, b.y, acc);
        acc = fmaf(a.z, b.z, acc);
        acc = fmaf(a.w, b.w, acc);
    }
    {
        const int i = 2048 + lane;
        if (i < N_VEC4) {
            const float4 a = xr[i];
            const float4 b = w4[i];
            acc = fmaf(a.x, b.x, acc);
            acc = fmaf(a.y, b.y, acc);
            acc = fmaf(a.z, b.z, acc);
            acc = fmaf(a.w, b.w, acc);
        }
    }

    // Warp reduction
    #pragma unroll
    for (int off = 16; off > 0; off >>= 1)
        acc += __shfl_xor_sync(0xFFFFFFFFu, acc, off);

    if (lane == 0) {
        const float s = fmaf(acc, g_inv_sum, -thr[0]);
        out[warp] = 1.0f / (1.0f + __expf(-s));
    }
}

extern "C" void kernel_launch(void* const* d_in, const int* in_sizes, int n_in,
                              void* d_out, int out_size) {
    const float* x    = (const float*)d_in[0];
    const float* wc   = (const float*)d_in[1];
    const float* wint = (const float*)d_in[2];
    const float* thr  = (const float*)d_in[3];
    float* out = (float*)d_out;

    const int rows = in_sizes[0] / N_TOT;

    choquet_prep_kernel<<<1, N_CRIT>>>(wc, wint);

    const int threads = 256;                 // 8 warps/block -> 8 rows/block
    const int blocks  = (rows + 7) / 8;
    choquet_gemv_kernel<<<blocks, threads>>>(x, thr, out, rows);
}

// round 2
// speedup vs baseline: 1.0145x; 1.0145x over previous
#include <cuda_runtime.h>
#include <math.h>

#define N_CRIT  128
#define N_PAIRS 8128
#define N_TOT   (N_CRIT + N_PAIRS)   // 8256
#define N_VEC4  (N_TOT / 4)          // 2064
#define MIN_W   1e-7f
#define PREP_T  1024

// Effective (constrained) weight vector: [wc_eff (128) | wint_eff (8128)]
__device__ float g_w[N_TOT];
__device__ float g_inv_sum;

// ---------------------------------------------------------------------------
// Prep: apply constraints, build contiguous weight vector, compute 1/sum.
// One block of 1024 threads; pairs distributed flat (8 per thread),
// (i,j) recovered from the pair index by triangle inversion.
// ---------------------------------------------------------------------------
__global__ void __launch_bounds__(PREP_T)
choquet_prep_kernel(const float* __restrict__ wc,
                    const float* __restrict__ wint) {
    __shared__ float s_wc[N_CRIT];
    __shared__ float s_part[PREP_T / 32];
    const int t = threadIdx.x;

    if (t < N_CRIT) {
        float wce = wc[t];
        if (wce < 0.f) wce = MIN_W;
        s_wc[t] = wce;
        g_w[t]  = wce;
    }
    __syncthreads();

    float sum = (t < N_CRIT) ? s_wc[t] : 0.f;

    // Pair p -> (i, j): p = i*(2*N-1-i)/2 + (j-i-1)
    // i = floor((2N-1 - sqrt((2N-1)^2 - 8p)) / 2), 2N-1 = 255
    #pragma unroll
    for (int k = 0; k < (N_PAIRS + PREP_T - 1) / PREP_T; k++) {
        const int p = t + k * PREP_T;
        if (p < N_PAIRS) {
            const float disc = sqrtf((float)(65025 - 8 * p));
            int i = (int)((255.0f - disc) * 0.5f);
            // guard against fp rounding at row boundaries
            int base = i * (2 * N_CRIT - 1 - i) / 2;
            if (base > p)                       { i--; base = i * (2 * N_CRIT - 1 - i) / 2; }
            else if (p - base >= N_CRIT - 1 - i){ i++; base = i * (2 * N_CRIT - 1 - i) / 2; }
            const int j = p - base + i + 1;
            const float lo = fmaxf(-s_wc[i], -s_wc[j]);
            const float v  = fmaxf(wint[p], lo);
            g_w[N_CRIT + p] = v;
            sum += v;
        }
    }

    // Block reduction: warp shuffle then shared
    #pragma unroll
    for (int off = 16; off > 0; off >>= 1)
        sum += __shfl_xor_sync(0xFFFFFFFFu, sum, off);
    if ((t & 31) == 0) s_part[t >> 5] = sum;
    __syncthreads();
    if (t < 32) {
        float v = (t < PREP_T / 32) ? s_part[t] : 0.f;
        #pragma unroll
        for (int off = 16; off > 0; off >>= 1)
            v += __shfl_xor_sync(0xFFFFFFFFu, v, off);
        if (t == 0) g_inv_sum = 1.0f / v;
    }
}

// ---------------------------------------------------------------------------
// GEMV: one warp per row. 2064 float4 per row. 4 independent accumulator
// chains + 4 batched streaming loads per outer iteration for high MLP.
// Epilogue: sigmoid(acc * inv_sum - thr).
// ---------------------------------------------------------------------------
__global__ void __launch_bounds__(256)
choquet_gemv_kernel(const float* __restrict__ x,
                    const float* __restrict__ thr,
                    float* __restrict__ out,
                    int rows) {
    const int warp = (blockIdx.x * blockDim.x + threadIdx.x) >> 5;
    const int lane = threadIdx.x & 31;
    if (warp >= rows) return;

    const float4* __restrict__ xr = reinterpret_cast<const float4*>(
        x + (size_t)warp * N_TOT);
    const float4* __restrict__ w4 = reinterpret_cast<const float4*>(g_w);

    float acc0 = 0.f, acc1 = 0.f, acc2 = 0.f, acc3 = 0.f;

    // 2064 = 16*128 + 16. Main loop: 16 outer iters, each lane does 4
    // strided float4 loads (batched -> MLP), 4 independent FMA chains.
    #pragma unroll 2
    for (int ii = 0; ii < 16; ii++) {
        const int b = ii * 128 + lane;
        const float4 a0 = __ldcs(&xr[b]);
        const float4 a1 = __ldcs(&xr[b + 32]);
        const float4 a2 = __ldcs(&xr[b + 64]);
        const float4 a3 = __ldcs(&xr[b + 96]);
        const float4 w0 = __ldg(&w4[b]);
        const float4 w1 = __ldg(&w4[b + 32]);
        const float4 w2 = __ldg(&w4[b + 64]);
        const float4 w3 = __ldg(&w4[b + 96]);
        acc0 = fmaf(a0.x, w0.x, acc0); acc0 = fmaf(a0.y, w0.y, acc0);
        acc0 = fmaf(a0.z, w0.z, acc0); acc0 = fmaf(a0.w, w0.w, acc0);
        acc1 = fmaf(a1.x, w1.x, acc1); acc1 = fmaf(a1.y, w1.y, acc1);
        acc1 = fmaf(a1.z, w1.z, acc1); acc1 = fmaf(a1.w, w1.w, acc1);
        acc2 = fmaf(a2.x, w2.x, acc2); acc2 = fmaf(a2.y, w2.y, acc2);
        acc2 = fmaf(a2.z, w2.z, acc2); acc2 = fmaf(a2.w, w2.w, acc2);
        acc3 = fmaf(a3.x, w3.x, acc3); acc3 = fmaf(a3.y, w3.y, acc3);
        acc3 = fmaf(a3.z, w3.z, acc3); acc3 = fmaf(a3.w, w3.w, acc3);
    }
    // Tail: 16 float4s (lanes 0..15)
    if (lane < 16) {
        const int b = 2048 + lane;
        const float4 a = __ldcs(&xr[b]);
        const float4 w = __ldg(&w4[b]);
        acc0 = fmaf(a.x, w.x, acc0); acc0 = fmaf(a.y, w.y, acc0);
        acc0 = fmaf(a.z, w.z, acc0); acc0 = fmaf(a.w, w.w, acc0);
    }

    float acc = (acc0 + acc1) + (acc2 + acc3);
    #pragma unroll
    for (int off = 16; off > 0; off >>= 1)
        acc += __shfl_xor_sync(0xFFFFFFFFu, acc, off);

    if (lane == 0) {
        const float s = fmaf(acc, g_inv_sum, -thr[0]);
        out[warp] = 1.0f / (1.0f + __expf(-s));
    }
}

extern "C" void kernel_launch(void* const* d_in, const int* in_sizes, int n_in,
                              void* d_out, int out_size) {
    const float* x    = (const float*)d_in[0];
    const float* wc   = (const float*)d_in[1];
    const float* wint = (const float*)d_in[2];
    const float* thr  = (const float*)d_in[3];
    float* out = (float*)d_out;

    const int rows = in_sizes[0] / N_TOT;

    choquet_prep_kernel<<<1, PREP_T>>>(wc, wint);

    const int threads = 256;                 // 8 warps/block -> 8 rows/block
    const int blocks  = (rows + 7) / 8;
    choquet_gemv_kernel<<<blocks, threads>>>(x, thr, out, rows);
}